// round 16
// baseline (speedup 1.0000x reference)
#include <cuda_runtime.h>
#include <cuda_fp16.h>
#include <math.h>
#include <stdint.h>

// Problem constants
#define Bc   16
#define NHc  16
#define DIMc 512
#define Lc   2304          // 48*48
#define NWc  64            // (48/6)^2
#define HID  2048          // 4*DIM
#define SCALEc 0.17677669529663689f   // 32^-0.5
#define NTOK (Bc*Lc)       // 36864
#define NKVQ 1536          // fused kv(1024) + q(512)
#define MPAD (NTOK + 128)  // 36992: +16 global tokens, padded to tile
#define NVALID (NTOK + 16) // rows that may be written to d_out

// ---------------- scratch (device globals; no allocation allowed) ----------
__device__ __half g_xnh [MPAD * DIMc];
__device__ __half g_kvqh[MPAD * NKVQ];
__device__ float  g_x1  [MPAD * DIMc];
__device__ __half g_h   [MPAD * HID];
// transposed ([N,K] row-major) fp16 weights
__device__ __half g_wkvqT[NKVQ * DIMc];
__device__ float  g_bkvq [NKVQ];
__device__ __half g_wfc1T[HID * DIMc];
__device__ __half g_wfc2T[DIMc * HID];
// precomputed rel-pos bias: [h][mq*37+mk]
__device__ float  g_biasM[NHc * 36 * 37];

__device__ __forceinline__ float gelu_exact(float v) {
    return 0.5f * v * (1.0f + erff(v * 0.70710678118654752440f));
}

#define CP16(dst, src) \
    asm volatile("cp.async.cg.shared.global [%0], [%1], 16;\n" :: "r"(dst), "l"(src))
#define CPCOMMIT() asm volatile("cp.async.commit_group;\n")
#define LDSM4(r0, r1, r2, r3, addr) \
    asm volatile("ldmatrix.sync.aligned.m8n8.x4.shared.b16 {%0,%1,%2,%3}, [%4];" \
                 : "=r"(r0), "=r"(r1), "=r"(r2), "=r"(r3) : "r"(addr))

// ---------------- fused weight prep: transposes + bias + rel-pos matrix ----
__global__ __launch_bounds__(256)
void prep_all(const float* __restrict__ w_kv,  const float* __restrict__ w_q,
              const float* __restrict__ w_fc1, const float* __restrict__ w_fc2,
              const float* __restrict__ b_kv,  const float* __restrict__ b_q,
              const float* __restrict__ table,
              __half* __restrict__ wkvqT, __half* __restrict__ wfc1T,
              __half* __restrict__ wfc2T, float* __restrict__ bkvq,
              float* __restrict__ biasM)
{
    int bid = blockIdx.x;
    const int t256 = threadIdx.y * 32 + threadIdx.x;
    if (bid == 2816) {
        for (int i = t256; i < NKVQ; i += 256)
            bkvq[i] = (i < 2 * DIMc) ? b_kv[i] : b_q[i - 2 * DIMc];
        return;
    }
    if (bid == 2817) {
        for (int i = t256; i < NHc * 36 * 37; i += 256) {
            const int h = i / 1332, p = i % 1332;
            const int mq = p / 37, mk = p % 37;
            int d0, d1;
            if (mk == 36) { d0 = mq % 6; d1 = mq / 6; }
            else          { d0 = mq % 6 - mk % 6; d1 = mq / 6 - mk / 6; }
            const int idx = (d0 + 5) * 11 + (d1 + 5);
            biasM[i] = table[idx * NHc + h];
        }
        return;
    }
    const float* src; __half* dst; int K, N;
    if (bid < 512)       { src = w_kv;  dst = wkvqT;              K = 512;  N = 1024; }
    else if (bid < 768)  { bid -= 512;  src = w_q;  dst = wkvqT + 1024 * 512; K = 512; N = 512; }
    else if (bid < 1792) { bid -= 768;  src = w_fc1; dst = wfc1T; K = 512;  N = 2048; }
    else                 { bid -= 1792; src = w_fc2; dst = wfc2T; K = 2048; N = 512;  }
    const int nTiles = N / 32;
    const int nb = (bid % nTiles) * 32;
    const int kb = (bid / nTiles) * 32;

    __shared__ float tile[32][33];
    const int tx = threadIdx.x, ty = threadIdx.y;
    #pragma unroll
    for (int i = ty; i < 32; i += 8)
        tile[i][tx] = src[(size_t)(kb + i) * N + nb + tx];
    __syncthreads();
    #pragma unroll
    for (int i = ty; i < 32; i += 8)
        dst[(size_t)(nb + i) * K + kb + tx] = __float2half_rn(tile[tx][i]);
}

// ---------------- LayerNorm over DIM=512 ------------------------------------
__global__ __launch_bounds__(128)
void ln_dual_h(const float* __restrict__ x, const float* __restrict__ xavg,
               const float* __restrict__ g, const float* __restrict__ be,
               __half* __restrict__ y)
{
    __shared__ float sS[4], sQ[4];
    const int t = blockIdx.x;
    const int tid = threadIdx.x;
    const float* src = (t < NTOK) ? (x + (size_t)t * DIMc)
                                  : (xavg + (size_t)(t - NTOK) * DIMc);
    const float4 v = ((const float4*)src)[tid];
    float s = v.x + v.y + v.z + v.w;
    float q = v.x*v.x + v.y*v.y + v.z*v.z + v.w*v.w;
    #pragma unroll
    for (int o = 16; o; o >>= 1) {
        s += __shfl_xor_sync(0xffffffffu, s, o);
        q += __shfl_xor_sync(0xffffffffu, q, o);
    }
    if ((tid & 31) == 0) { sS[tid >> 5] = s; sQ[tid >> 5] = q; }
    __syncthreads();
    const float S = sS[0] + sS[1] + sS[2] + sS[3];
    const float Q = sQ[0] + sQ[1] + sQ[2] + sQ[3];
    const float mean = S * (1.0f / 512.0f);
    const float var  = Q * (1.0f / 512.0f) - mean * mean;
    const float rstd = rsqrtf(var + 1e-3f);
    const float4 gg = ((const float4*)g)[tid];
    const float4 bb = ((const float4*)be)[tid];
    __half2 h0 = __floats2half2_rn((v.x - mean) * rstd * gg.x + bb.x,
                                   (v.y - mean) * rstd * gg.y + bb.y);
    __half2 h1 = __floats2half2_rn((v.z - mean) * rstd * gg.z + bb.z,
                                   (v.w - mean) * rstd * gg.w + bb.w);
    __half2* yp = (__half2*)(y + (size_t)t * DIMc);
    yp[tid * 2 + 0] = h0;
    yp[tid * 2 + 1] = h1;
}

__global__ __launch_bounds__(128)
void ln_kernel_h(const float* __restrict__ x, const float* __restrict__ g,
                 const float* __restrict__ be, __half* __restrict__ y)
{
    __shared__ float sS[4], sQ[4];
    const int t = blockIdx.x;
    const int tid = threadIdx.x;
    const float4 v = ((const float4*)(x + (size_t)t * DIMc))[tid];
    float s = v.x + v.y + v.z + v.w;
    float q = v.x*v.x + v.y*v.y + v.z*v.z + v.w*v.w;
    #pragma unroll
    for (int o = 16; o; o >>= 1) {
        s += __shfl_xor_sync(0xffffffffu, s, o);
        q += __shfl_xor_sync(0xffffffffu, q, o);
    }
    if ((tid & 31) == 0) { sS[tid >> 5] = s; sQ[tid >> 5] = q; }
    __syncthreads();
    const float S = sS[0] + sS[1] + sS[2] + sS[3];
    const float Q = sQ[0] + sQ[1] + sQ[2] + sQ[3];
    const float mean = S * (1.0f / 512.0f);
    const float var  = Q * (1.0f / 512.0f) - mean * mean;
    const float rstd = rsqrtf(var + 1e-3f);
    const float4 gg = ((const float4*)g)[tid];
    const float4 bb = ((const float4*)be)[tid];
    __half2 h0 = __floats2half2_rn((v.x - mean) * rstd * gg.x + bb.x,
                                   (v.y - mean) * rstd * gg.y + bb.y);
    __half2 h1 = __floats2half2_rn((v.z - mean) * rstd * gg.z + bb.z,
                                   (v.w - mean) * rstd * gg.w + bb.w);
    __half2* yp = (__half2*)(y + (size_t)t * DIMc);
    yp[tid * 2 + 0] = h0;
    yp[tid * 2 + 1] = h1;
}

// ---------------- fp16 tensor-core GEMM: 128x128 tile, 4-stage -------------
template<int ACT, bool RES, bool OUTH>
__global__ __launch_bounds__(256, 2)
void hgemm(int M, int N, int K, int Mv,
           const __half* __restrict__ A, const __half* __restrict__ WT,
           const float* __restrict__ bias, const float* __restrict__ R,
           void* __restrict__ Cv)
{
    constexpr int BM = 128, BN = 128, BK = 32;   // BK in halfs
    constexpr int PAD = 40;                       // halfs per smem row
    constexpr int STG = 4;
    constexpr uint32_t A_BYTES  = (uint32_t)BM * PAD * 2u;          // 10240
    constexpr uint32_t ST_BYTES = (uint32_t)(BM + BN) * PAD * 2u;   // 20480

    extern __shared__ __align__(16) __half smem[];

    const int tid  = threadIdx.x;
    const int lane = tid & 31;
    const int warp = tid >> 5;
    const int wm   = warp >> 2;
    const int wn   = warp & 3;
    const int bm   = blockIdx.y * BM;
    const int bn   = blockIdx.x * BN;

    const uint32_t sb = (uint32_t)__cvta_generic_to_shared(smem);

    const int l_r = tid >> 1;
    const int l_o = (tid & 1) << 4;
    const __half* a_src = A  + (size_t)(bm + l_r) * K + l_o;
    const __half* b_src = WT + (size_t)(bn + l_r) * K + l_o;
    const uint32_t a_dst = sb + (uint32_t)(l_r * PAD + l_o) * 2u;
    const uint32_t b_dst = sb + A_BYTES + (uint32_t)(l_r * PAD + l_o) * 2u;

    uint32_t aLd[4];
    #pragma unroll
    for (int mt = 0; mt < 4; mt++) {
        const int row = wm * 64 + mt * 16 + (lane & 15);
        const int col = (lane >> 4) * 8;
        aLd[mt] = sb + (uint32_t)(row * PAD + col) * 2u;
    }
    uint32_t bLd[2];
    #pragma unroll
    for (int ng = 0; ng < 2; ng++) {
        const int row = wn * 32 + ng * 16 + (lane & 7) + (lane >> 4) * 8;
        const int col = ((lane >> 3) & 1) * 8;
        bLd[ng] = sb + A_BYTES + (uint32_t)(row * PAD + col) * 2u;
    }

    float acc[4][4][4] = {};
    const int T = K / BK;

    #pragma unroll
    for (int s = 0; s < STG - 1; s++) {
        const uint32_t o = (uint32_t)s * ST_BYTES;
        const int k0 = s * BK;
        CP16(a_dst + o, a_src + k0); CP16(a_dst + o + 16u, a_src + k0 + 8);
        CP16(b_dst + o, b_src + k0); CP16(b_dst + o + 16u, b_src + k0 + 8);
        CPCOMMIT();
    }

    for (int t = 0; t < T; t++) {
        asm volatile("cp.async.wait_group 2;\n");
        __syncthreads();

        if (t + STG - 1 < T) {
            const int k0 = (t + STG - 1) * BK;
            const uint32_t o = (uint32_t)((t + STG - 1) % STG) * ST_BYTES;
            CP16(a_dst + o, a_src + k0); CP16(a_dst + o + 16u, a_src + k0 + 8);
            CP16(b_dst + o, b_src + k0); CP16(b_dst + o + 16u, b_src + k0 + 8);
        }
        CPCOMMIT();

        const uint32_t so = (uint32_t)(t % STG) * ST_BYTES;

        uint32_t af[2][4][4];
        uint32_t bf[2][4][2];
        #pragma unroll
        for (int ks2 = 0; ks2 < 2; ks2++) {
            const uint32_t ko = so + (uint32_t)(ks2 * 16) * 2u;
            #pragma unroll
            for (int mt = 0; mt < 4; mt++)
                LDSM4(af[ks2][mt][0], af[ks2][mt][1], af[ks2][mt][2], af[ks2][mt][3],
                      aLd[mt] + ko);
            #pragma unroll
            for (int ng = 0; ng < 2; ng++)
                LDSM4(bf[ks2][2*ng][0], bf[ks2][2*ng][1], bf[ks2][2*ng+1][0], bf[ks2][2*ng+1][1],
                      bLd[ng] + ko);
        }
        #pragma unroll
        for (int ks2 = 0; ks2 < 2; ks2++)
            #pragma unroll
            for (int mt = 0; mt < 4; mt++)
                #pragma unroll
                for (int nt = 0; nt < 4; nt++)
                    asm volatile(
                        "mma.sync.aligned.m16n8k16.row.col.f32.f16.f16.f32 "
                        "{%0,%1,%2,%3}, {%4,%5,%6,%7}, {%8,%9}, {%0,%1,%2,%3};\n"
                        : "+f"(acc[mt][nt][0]), "+f"(acc[mt][nt][1]),
                          "+f"(acc[mt][nt][2]), "+f"(acc[mt][nt][3])
                        : "r"(af[ks2][mt][0]), "r"(af[ks2][mt][1]),
                          "r"(af[ks2][mt][2]), "r"(af[ks2][mt][3]),
                          "r"(bf[ks2][nt][0]), "r"(bf[ks2][nt][1]));
    }

    float* Cf = (float*)Cv;
    __half* Ch = (__half*)Cv;
    #pragma unroll
    for (int mt = 0; mt < 4; mt++) {
        #pragma unroll
        for (int nt = 0; nt < 4; nt++) {
            const int r0 = bm + wm * 64 + mt * 16 + (lane >> 2);
            const int c  = bn + wn * 32 + nt * 8 + (lane & 3) * 2;
            const float bx = bias[c], by = bias[c + 1];
            #pragma unroll
            for (int half_ = 0; half_ < 2; half_++) {
                const int r = r0 + half_ * 8;
                if (r >= Mv) continue;
                float vx = acc[mt][nt][half_ * 2 + 0] + bx;
                float vy = acc[mt][nt][half_ * 2 + 1] + by;
                if (ACT == 1) { vx = gelu_exact(vx); vy = gelu_exact(vy); }
                if (RES) {
                    const float2 rr = *(const float2*)(R + (size_t)r * N + c);
                    vx += rr.x; vy += rr.y;
                }
                if (OUTH) {
                    *(__half2*)(Ch + (size_t)r * N + c) = __floats2half2_rn(vx, vy);
                } else {
                    float2 o; o.x = vx; o.y = vy;
                    *(float2*)(Cf + (size_t)r * N + c) = o;
                }
            }
        }
    }
}

// ---------------- fused attention: window (bx<1024) + global (bx>=1024) ----
__global__ __launch_bounds__(128)
void attn_fused(const __half* __restrict__ kvq, const float* __restrict__ biasM,
                const float* __restrict__ xin, const float* __restrict__ xavg_in,
                float* __restrict__ x1)
{
    __shared__ __align__(16) char smu[14160];
    const int bx = blockIdx.x;
    const int h  = blockIdx.y;
    const int tid = threadIdx.x;

    if (bx < 1024) {
        // ---------------- window attention (R15 layout + precomputed bias) --
        const int b  = bx >> 6;
        const int wi = bx & 63;
        const int wr = wi >> 3, wc = wi & 7;

        uint4 (*qs4)[5] = (uint4(*)[5])(smu);            // 36*5*16 = 2880
        uint4 (*ks4)[5] = (uint4(*)[5])(smu + 2880);     // 37*5*16 = 2960
        uint4 (*vs4)[5] = (uint4(*)[5])(smu + 5840);     // 2960
        float (*sc)[37] = (float(*)[37])(smu + 8800);    // 36*37*4 = 5328

        for (int idx = tid; idx < 37 * 4; idx += 128) {
            const int m = idx >> 2, c = idx & 3;
            size_t row;
            if (m < 36) {
                const int r = m / 6, cc = m % 6;
                row = (size_t)(b * Lc + (wr * 6 + r) * 48 + wc * 6 + cc);
            } else {
                row = (size_t)(NTOK + b);
            }
            const uint4* base = (const uint4*)(kvq + row * NKVQ + h * 32);
            ks4[m][c] = base[c];
            vs4[m][c] = base[c + DIMc / 8];
            if (m < 36) qs4[m][c] = base[c + 2 * (DIMc / 8)];
        }
        __syncthreads();

        const float* biasH = biasM + h * 1332;

        for (int t = tid; t < 18 * 19; t += 128) {
            const int mq0 = (t / 19) * 2;
            const int mk0 = (t % 19) * 2;
            const int mk1 = (mk0 + 1 < 37) ? (mk0 + 1) : 36;
            float a00 = 0.f, a01 = 0.f, a10 = 0.f, a11 = 0.f;
            #pragma unroll
            for (int c = 0; c < 4; c++) {
                const uint4 q0 = qs4[mq0][c],   q1 = qs4[mq0 + 1][c];
                const uint4 k0 = ks4[mk0][c],   k1 = ks4[mk1][c];
                const __half2* q0h = (const __half2*)&q0;
                const __half2* q1h = (const __half2*)&q1;
                const __half2* k0h = (const __half2*)&k0;
                const __half2* k1h = (const __half2*)&k1;
                #pragma unroll
                for (int j = 0; j < 4; j++) {
                    const float2 qa = __half22float2(q0h[j]);
                    const float2 qb = __half22float2(q1h[j]);
                    const float2 ka = __half22float2(k0h[j]);
                    const float2 kb = __half22float2(k1h[j]);
                    a00 = fmaf(qa.x, ka.x, a00); a00 = fmaf(qa.y, ka.y, a00);
                    a01 = fmaf(qa.x, kb.x, a01); a01 = fmaf(qa.y, kb.y, a01);
                    a10 = fmaf(qb.x, ka.x, a10); a10 = fmaf(qb.y, ka.y, a10);
                    a11 = fmaf(qb.x, kb.x, a11); a11 = fmaf(qb.y, kb.y, a11);
                }
            }
            sc[mq0][mk0]     = a00 * SCALEc + biasH[mq0 * 37 + mk0];
            sc[mq0 + 1][mk0] = a10 * SCALEc + biasH[(mq0 + 1) * 37 + mk0];
            if (mk0 + 1 < 37) {
                sc[mq0][mk0 + 1]     = a01 * SCALEc + biasH[mq0 * 37 + mk0 + 1];
                sc[mq0 + 1][mk0 + 1] = a11 * SCALEc + biasH[(mq0 + 1) * 37 + mk0 + 1];
            }
        }
        __syncthreads();

        if (tid < 36) {
            float mx = -1e30f;
            #pragma unroll
            for (int k = 0; k < 37; k++) mx = fmaxf(mx, sc[tid][k]);
            float sum = 0.0f;
            #pragma unroll
            for (int k = 0; k < 37; k++) { const float e = expf(sc[tid][k] - mx); sc[tid][k] = e; sum += e; }
            const float inv = 1.0f / sum;
            #pragma unroll
            for (int k = 0; k < 37; k++) sc[tid][k] *= inv;
        }
        __syncthreads();

        for (int p = tid; p < 18 * 4; p += 128) {
            const int m0 = (p >> 2) * 2, c = p & 3;
            float acc0[8] = {}, acc1[8] = {};
            #pragma unroll 4
            for (int k = 0; k < 37; k++) {
                const float w0 = sc[m0][k];
                const float w1 = sc[m0 + 1][k];
                const uint4 vv = vs4[k][c];
                const __half2* vh = (const __half2*)&vv;
                #pragma unroll
                for (int j = 0; j < 4; j++) {
                    const float2 vf = __half22float2(vh[j]);
                    acc0[2*j]   = fmaf(w0, vf.x, acc0[2*j]);
                    acc0[2*j+1] = fmaf(w0, vf.y, acc0[2*j+1]);
                    acc1[2*j]   = fmaf(w1, vf.x, acc1[2*j]);
                    acc1[2*j+1] = fmaf(w1, vf.y, acc1[2*j+1]);
                }
            }
            #pragma unroll
            for (int i = 0; i < 2; i++) {
                const int m = m0 + i;
                const float* acc = (i == 0) ? acc0 : acc1;
                const int r = m / 6, cc = m % 6;
                const int l = (wr * 6 + r) * 48 + wc * 6 + cc;
                const size_t o = (size_t)(b * Lc + l) * DIMc + h * 32 + c * 8;
                float4 i0 = *(const float4*)(xin + o);
                float4 i1 = *(const float4*)(xin + o + 4);
                i0.x += acc[0]; i0.y += acc[1]; i0.z += acc[2]; i0.w += acc[3];
                i1.x += acc[4]; i1.y += acc[5]; i1.z += acc[6]; i1.w += acc[7];
                *(float4*)(x1 + o) = i0;
                *(float4*)(x1 + o + 4) = i1;
            }
        }
    } else {
        // ---------------- global-token attention (128 threads) --------------
        const int b = bx - 1024;
        float* qsh = (float*)smu;              // 32
        float* wgt = (float*)(smu + 128);      // Lc
        float* red = (float*)(smu + 128 + Lc * 4);  // 4
        const int lane = tid & 31, wn = tid >> 5;

        if (tid < 32)
            qsh[tid] = __half2float(kvq[(size_t)(NTOK + b) * NKVQ + 2 * DIMc + h * 32 + tid]) * SCALEc;
        __syncthreads();

        float lmax = -1e30f;
        for (int k = tid; k < Lc; k += 128) {
            const __half2* kp = (const __half2*)(kvq + (size_t)(b * Lc + k) * NKVQ + h * 32);
            float acc = 0.0f;
            #pragma unroll
            for (int d2 = 0; d2 < 16; d2++) {
                const float2 kk = __half22float2(kp[d2]);
                acc = fmaf(qsh[d2*2+0], kk.x, acc);
                acc = fmaf(qsh[d2*2+1], kk.y, acc);
            }
            wgt[k] = acc;
            lmax = fmaxf(lmax, acc);
        }
        #pragma unroll
        for (int o = 16; o; o >>= 1) lmax = fmaxf(lmax, __shfl_xor_sync(0xffffffffu, lmax, o));
        if (lane == 0) red[wn] = lmax;
        __syncthreads();
        float gmax = fmaxf(fmaxf(red[0], red[1]), fmaxf(red[2], red[3]));
        __syncthreads();

        float lsum = 0.0f;
        for (int k = tid; k < Lc; k += 128) {
            const float e = expf(wgt[k] - gmax);
            wgt[k] = e;
            lsum += e;
        }
        #pragma unroll
        for (int o = 16; o; o >>= 1) lsum += __shfl_xor_sync(0xffffffffu, lsum, o);
        if (lane == 0) red[wn] = lsum;
        __syncthreads();
        const float inv = 1.0f / (red[0] + red[1] + red[2] + red[3]);

        float acc[8] = {};
        for (int k = lane; k < Lc; k += 32) {
            const float wk = wgt[k];
            const __half2* vv = (const __half2*)(kvq + (size_t)(b * Lc + k) * NKVQ + DIMc + h * 32 + wn * 8);
            #pragma unroll
            for (int j = 0; j < 4; j++) {
                const float2 vf = __half22float2(vv[j]);
                acc[2*j]   = fmaf(wk, vf.x, acc[2*j]);
                acc[2*j+1] = fmaf(wk, vf.y, acc[2*j+1]);
            }
        }
        #pragma unroll
        for (int j = 0; j < 8; j++) {
            #pragma unroll
            for (int o = 16; o; o >>= 1) acc[j] += __shfl_xor_sync(0xffffffffu, acc[j], o);
        }
        if (lane == 0) {
            #pragma unroll
            for (int j = 0; j < 8; j++) {
                const int c = h * 32 + wn * 8 + j;
                x1[(size_t)(NTOK + b) * DIMc + c] = xavg_in[(size_t)b * DIMc + c] + acc[j] * inv;
            }
        }
    }
}

// ---------------------------------------------------------------------------
extern "C" void kernel_launch(void* const* d_in, const int* in_sizes, int n_in,
                              void* d_out, int out_size)
{
    const float* x     = (const float*)d_in[0];
    const float* xavg  = (const float*)d_in[1];
    const float* w_kv  = (const float*)d_in[2];
    const float* b_kv  = (const float*)d_in[3];
    const float* w_q   = (const float*)d_in[4];
    const float* b_q   = (const float*)d_in[5];
    const float* table = (const float*)d_in[6];
    const float* g1    = (const float*)d_in[7];
    const float* be1   = (const float*)d_in[8];
    const float* g2    = (const float*)d_in[9];
    const float* be2   = (const float*)d_in[10];
    const float* w_fc1 = (const float*)d_in[11];
    const float* b_fc1 = (const float*)d_in[12];
    const float* w_fc2 = (const float*)d_in[13];
    const float* b_fc2 = (const float*)d_in[14];
    float* out = (float*)d_out;

    __half *xnh, *kvqh, *hbuf, *wkvqT, *wfc1T, *wfc2T;
    float *x1, *bkvq, *biasM;
    cudaGetSymbolAddress((void**)&xnh,    g_xnh);
    cudaGetSymbolAddress((void**)&kvqh,   g_kvqh);
    cudaGetSymbolAddress((void**)&x1,     g_x1);
    cudaGetSymbolAddress((void**)&hbuf,   g_h);
    cudaGetSymbolAddress((void**)&wkvqT,  g_wkvqT);
    cudaGetSymbolAddress((void**)&bkvq,   g_bkvq);
    cudaGetSymbolAddress((void**)&wfc1T,  g_wfc1T);
    cudaGetSymbolAddress((void**)&wfc2T,  g_wfc2T);
    cudaGetSymbolAddress((void**)&biasM,  g_biasM);

    // dynamic smem: 4 stages x 256 rows x 40 halfs x 2B = 81920 B
    const int SMEM_SZ = 4 * 256 * 40 * 2;
    cudaFuncSetAttribute(hgemm<0, false, true >, cudaFuncAttributeMaxDynamicSharedMemorySize, SMEM_SZ);
    cudaFuncSetAttribute(hgemm<1, false, true >, cudaFuncAttributeMaxDynamicSharedMemorySize, SMEM_SZ);
    cudaFuncSetAttribute(hgemm<0, true,  false>, cudaFuncAttributeMaxDynamicSharedMemorySize, SMEM_SZ);

    // 0. fused weight prep (+ rel-pos bias matrix)
    prep_all<<<2818, dim3(32, 8)>>>(w_kv, w_q, w_fc1, w_fc2, b_kv, b_q, table,
                                    wkvqT, wfc1T, wfc2T, bkvq, biasM);

    // 1. LayerNorm 1 (image + global in one launch)
    ln_dual_h<<<NVALID, 128>>>(x, xavg, g1, be1, xnh);

    // 2. Fused kvq projection over ALL tokens in one GEMM
    hgemm<0, false, true><<<dim3(NKVQ/128, MPAD/128), 256, SMEM_SZ>>>(
        MPAD, NKVQ, DIMc, MPAD, xnh, wkvqT, bkvq, nullptr, kvqh);

    // 3. Attention (+ residual): window + global in one launch
    attn_fused<<<dim3(Bc*NWc + Bc, NHc), 128>>>(kvqh, biasM, x, xavg, x1);

    // 4. LayerNorm 2
    ln_kernel_h<<<NVALID, 128>>>(x1, g2, be2, xnh);

    // 5. MLP (+ residual)
    hgemm<1, false, true ><<<dim3(HID/128,  MPAD/128), 256, SMEM_SZ>>>(
        MPAD, HID,  DIMc, MPAD,   xnh,  wfc1T, b_fc1, nullptr, hbuf);
    hgemm<0, true,  false><<<dim3(DIMc/128, MPAD/128), 256, SMEM_SZ>>>(
        MPAD, DIMc, HID,  NVALID, hbuf, wfc2T, b_fc2, x1, out);
}

// round 17
// speedup vs baseline: 1.0554x; 1.0554x over previous
#include <cuda_runtime.h>
#include <cuda_fp16.h>
#include <math.h>
#include <stdint.h>

// Problem constants
#define Bc   16
#define NHc  16
#define DIMc 512
#define Lc   2304          // 48*48
#define NWc  64            // (48/6)^2
#define HID  2048          // 4*DIM
#define SCALEc 0.17677669529663689f   // 32^-0.5
#define NTOK (Bc*Lc)       // 36864
#define NKVQ 1536          // fused kv(1024) + q(512)
#define MPAD (NTOK + 128)  // 36992: +16 global tokens, padded to tile
#define NVALID (NTOK + 16) // rows that may be written to d_out

// ---------------- scratch (device globals; no allocation allowed) ----------
__device__ __half g_xnh [MPAD * DIMc];
__device__ __half g_kvqh[MPAD * NKVQ];
__device__ float  g_x1  [MPAD * DIMc];
__device__ __half g_h   [MPAD * HID];
// transposed ([N,K] row-major) fp16 weights
__device__ __half g_wkvqT[NKVQ * DIMc];
__device__ float  g_bkvq [NKVQ];
__device__ __half g_wfc1T[HID * DIMc];
__device__ __half g_wfc2T[DIMc * HID];
// precomputed rel-pos bias: [h][mq*37+mk]
__device__ float  g_biasM[NHc * 36 * 37];

__device__ __forceinline__ float gelu_exact(float v) {
    return 0.5f * v * (1.0f + erff(v * 0.70710678118654752440f));
}

#define CP16(dst, src) \
    asm volatile("cp.async.cg.shared.global [%0], [%1], 16;\n" :: "r"(dst), "l"(src))
#define CPCOMMIT() asm volatile("cp.async.commit_group;\n")
#define LDSM4(r0, r1, r2, r3, addr) \
    asm volatile("ldmatrix.sync.aligned.m8n8.x4.shared.b16 {%0,%1,%2,%3}, [%4];" \
                 : "=r"(r0), "=r"(r1), "=r"(r2), "=r"(r3) : "r"(addr))

// ---------------- fused weight prep: transposes + bias + rel-pos matrix ----
__global__ __launch_bounds__(256)
void prep_all(const float* __restrict__ w_kv,  const float* __restrict__ w_q,
              const float* __restrict__ w_fc1, const float* __restrict__ w_fc2,
              const float* __restrict__ b_kv,  const float* __restrict__ b_q,
              const float* __restrict__ table,
              __half* __restrict__ wkvqT, __half* __restrict__ wfc1T,
              __half* __restrict__ wfc2T, float* __restrict__ bkvq,
              float* __restrict__ biasM)
{
    int bid = blockIdx.x;
    const int t256 = threadIdx.y * 32 + threadIdx.x;
    if (bid == 2816) {
        for (int i = t256; i < NKVQ; i += 256)
            bkvq[i] = (i < 2 * DIMc) ? b_kv[i] : b_q[i - 2 * DIMc];
        return;
    }
    if (bid == 2817) {
        for (int i = t256; i < NHc * 36 * 37; i += 256) {
            const int h = i / 1332, p = i % 1332;
            const int mq = p / 37, mk = p % 37;
            int d0, d1;
            if (mk == 36) { d0 = mq % 6; d1 = mq / 6; }
            else          { d0 = mq % 6 - mk % 6; d1 = mq / 6 - mk / 6; }
            const int idx = (d0 + 5) * 11 + (d1 + 5);
            biasM[i] = table[idx * NHc + h];
        }
        return;
    }
    const float* src; __half* dst; int K, N;
    if (bid < 512)       { src = w_kv;  dst = wkvqT;              K = 512;  N = 1024; }
    else if (bid < 768)  { bid -= 512;  src = w_q;  dst = wkvqT + 1024 * 512; K = 512; N = 512; }
    else if (bid < 1792) { bid -= 768;  src = w_fc1; dst = wfc1T; K = 512;  N = 2048; }
    else                 { bid -= 1792; src = w_fc2; dst = wfc2T; K = 2048; N = 512;  }
    const int nTiles = N / 32;
    const int nb = (bid % nTiles) * 32;
    const int kb = (bid / nTiles) * 32;

    __shared__ float tile[32][33];
    const int tx = threadIdx.x, ty = threadIdx.y;
    #pragma unroll
    for (int i = ty; i < 32; i += 8)
        tile[i][tx] = src[(size_t)(kb + i) * N + nb + tx];
    __syncthreads();
    #pragma unroll
    for (int i = ty; i < 32; i += 8)
        dst[(size_t)(nb + i) * K + kb + tx] = __float2half_rn(tile[tx][i]);
}

// ---------------- LayerNorm over DIM=512 ------------------------------------
__global__ __launch_bounds__(128)
void ln_dual_h(const float* __restrict__ x, const float* __restrict__ xavg,
               const float* __restrict__ g, const float* __restrict__ be,
               __half* __restrict__ y)
{
    __shared__ float sS[4], sQ[4];
    const int t = blockIdx.x;
    const int tid = threadIdx.x;
    const float* src = (t < NTOK) ? (x + (size_t)t * DIMc)
                                  : (xavg + (size_t)(t - NTOK) * DIMc);
    const float4 v = ((const float4*)src)[tid];
    float s = v.x + v.y + v.z + v.w;
    float q = v.x*v.x + v.y*v.y + v.z*v.z + v.w*v.w;
    #pragma unroll
    for (int o = 16; o; o >>= 1) {
        s += __shfl_xor_sync(0xffffffffu, s, o);
        q += __shfl_xor_sync(0xffffffffu, q, o);
    }
    if ((tid & 31) == 0) { sS[tid >> 5] = s; sQ[tid >> 5] = q; }
    __syncthreads();
    const float S = sS[0] + sS[1] + sS[2] + sS[3];
    const float Q = sQ[0] + sQ[1] + sQ[2] + sQ[3];
    const float mean = S * (1.0f / 512.0f);
    const float var  = Q * (1.0f / 512.0f) - mean * mean;
    const float rstd = rsqrtf(var + 1e-3f);
    const float4 gg = ((const float4*)g)[tid];
    const float4 bb = ((const float4*)be)[tid];
    __half2 h0 = __floats2half2_rn((v.x - mean) * rstd * gg.x + bb.x,
                                   (v.y - mean) * rstd * gg.y + bb.y);
    __half2 h1 = __floats2half2_rn((v.z - mean) * rstd * gg.z + bb.z,
                                   (v.w - mean) * rstd * gg.w + bb.w);
    __half2* yp = (__half2*)(y + (size_t)t * DIMc);
    yp[tid * 2 + 0] = h0;
    yp[tid * 2 + 1] = h1;
}

__global__ __launch_bounds__(128)
void ln_kernel_h(const float* __restrict__ x, const float* __restrict__ g,
                 const float* __restrict__ be, __half* __restrict__ y)
{
    __shared__ float sS[4], sQ[4];
    const int t = blockIdx.x;
    const int tid = threadIdx.x;
    const float4 v = ((const float4*)(x + (size_t)t * DIMc))[tid];
    float s = v.x + v.y + v.z + v.w;
    float q = v.x*v.x + v.y*v.y + v.z*v.z + v.w*v.w;
    #pragma unroll
    for (int o = 16; o; o >>= 1) {
        s += __shfl_xor_sync(0xffffffffu, s, o);
        q += __shfl_xor_sync(0xffffffffu, q, o);
    }
    if ((tid & 31) == 0) { sS[tid >> 5] = s; sQ[tid >> 5] = q; }
    __syncthreads();
    const float S = sS[0] + sS[1] + sS[2] + sS[3];
    const float Q = sQ[0] + sQ[1] + sQ[2] + sQ[3];
    const float mean = S * (1.0f / 512.0f);
    const float var  = Q * (1.0f / 512.0f) - mean * mean;
    const float rstd = rsqrtf(var + 1e-3f);
    const float4 gg = ((const float4*)g)[tid];
    const float4 bb = ((const float4*)be)[tid];
    __half2 h0 = __floats2half2_rn((v.x - mean) * rstd * gg.x + bb.x,
                                   (v.y - mean) * rstd * gg.y + bb.y);
    __half2 h1 = __floats2half2_rn((v.z - mean) * rstd * gg.z + bb.z,
                                   (v.w - mean) * rstd * gg.w + bb.w);
    __half2* yp = (__half2*)(y + (size_t)t * DIMc);
    yp[tid * 2 + 0] = h0;
    yp[tid * 2 + 1] = h1;
}

// ---------------- fp16 tensor-core GEMM: 128x128 tile, 4-stage -------------
template<int ACT, bool RES, bool OUTH>
__global__ __launch_bounds__(256, 2)
void hgemm(int M, int N, int K, int Mv,
           const __half* __restrict__ A, const __half* __restrict__ WT,
           const float* __restrict__ bias, const float* __restrict__ R,
           void* __restrict__ Cv)
{
    constexpr int BM = 128, BN = 128, BK = 32;   // BK in halfs
    constexpr int PAD = 40;                       // halfs per smem row
    constexpr int STG = 4;
    constexpr uint32_t A_BYTES  = (uint32_t)BM * PAD * 2u;          // 10240
    constexpr uint32_t ST_BYTES = (uint32_t)(BM + BN) * PAD * 2u;   // 20480

    extern __shared__ __align__(16) __half smem[];

    const int tid  = threadIdx.x;
    const int lane = tid & 31;
    const int warp = tid >> 5;
    const int wm   = warp >> 2;
    const int wn   = warp & 3;
    const int bm   = blockIdx.y * BM;
    const int bn   = blockIdx.x * BN;

    const uint32_t sb = (uint32_t)__cvta_generic_to_shared(smem);

    const int l_r = tid >> 1;
    const int l_o = (tid & 1) << 4;
    const __half* a_src = A  + (size_t)(bm + l_r) * K + l_o;
    const __half* b_src = WT + (size_t)(bn + l_r) * K + l_o;
    const uint32_t a_dst = sb + (uint32_t)(l_r * PAD + l_o) * 2u;
    const uint32_t b_dst = sb + A_BYTES + (uint32_t)(l_r * PAD + l_o) * 2u;

    uint32_t aLd[4];
    #pragma unroll
    for (int mt = 0; mt < 4; mt++) {
        const int row = wm * 64 + mt * 16 + (lane & 15);
        const int col = (lane >> 4) * 8;
        aLd[mt] = sb + (uint32_t)(row * PAD + col) * 2u;
    }
    uint32_t bLd[2];
    #pragma unroll
    for (int ng = 0; ng < 2; ng++) {
        const int row = wn * 32 + ng * 16 + (lane & 7) + (lane >> 4) * 8;
        const int col = ((lane >> 3) & 1) * 8;
        bLd[ng] = sb + A_BYTES + (uint32_t)(row * PAD + col) * 2u;
    }

    float acc[4][4][4] = {};
    const int T = K / BK;

    #pragma unroll
    for (int s = 0; s < STG - 1; s++) {
        const uint32_t o = (uint32_t)s * ST_BYTES;
        const int k0 = s * BK;
        CP16(a_dst + o, a_src + k0); CP16(a_dst + o + 16u, a_src + k0 + 8);
        CP16(b_dst + o, b_src + k0); CP16(b_dst + o + 16u, b_src + k0 + 8);
        CPCOMMIT();
    }

    for (int t = 0; t < T; t++) {
        asm volatile("cp.async.wait_group 2;\n");
        __syncthreads();

        if (t + STG - 1 < T) {
            const int k0 = (t + STG - 1) * BK;
            const uint32_t o = (uint32_t)((t + STG - 1) % STG) * ST_BYTES;
            CP16(a_dst + o, a_src + k0); CP16(a_dst + o + 16u, a_src + k0 + 8);
            CP16(b_dst + o, b_src + k0); CP16(b_dst + o + 16u, b_src + k0 + 8);
        }
        CPCOMMIT();

        const uint32_t so = (uint32_t)(t % STG) * ST_BYTES;

        uint32_t af[2][4][4];
        uint32_t bf[2][4][2];
        #pragma unroll
        for (int ks2 = 0; ks2 < 2; ks2++) {
            const uint32_t ko = so + (uint32_t)(ks2 * 16) * 2u;
            #pragma unroll
            for (int mt = 0; mt < 4; mt++)
                LDSM4(af[ks2][mt][0], af[ks2][mt][1], af[ks2][mt][2], af[ks2][mt][3],
                      aLd[mt] + ko);
            #pragma unroll
            for (int ng = 0; ng < 2; ng++)
                LDSM4(bf[ks2][2*ng][0], bf[ks2][2*ng][1], bf[ks2][2*ng+1][0], bf[ks2][2*ng+1][1],
                      bLd[ng] + ko);
        }
        #pragma unroll
        for (int ks2 = 0; ks2 < 2; ks2++)
            #pragma unroll
            for (int mt = 0; mt < 4; mt++)
                #pragma unroll
                for (int nt = 0; nt < 4; nt++)
                    asm volatile(
                        "mma.sync.aligned.m16n8k16.row.col.f32.f16.f16.f32 "
                        "{%0,%1,%2,%3}, {%4,%5,%6,%7}, {%8,%9}, {%0,%1,%2,%3};\n"
                        : "+f"(acc[mt][nt][0]), "+f"(acc[mt][nt][1]),
                          "+f"(acc[mt][nt][2]), "+f"(acc[mt][nt][3])
                        : "r"(af[ks2][mt][0]), "r"(af[ks2][mt][1]),
                          "r"(af[ks2][mt][2]), "r"(af[ks2][mt][3]),
                          "r"(bf[ks2][nt][0]), "r"(bf[ks2][nt][1]));
    }

    float* Cf = (float*)Cv;
    __half* Ch = (__half*)Cv;
    #pragma unroll
    for (int mt = 0; mt < 4; mt++) {
        #pragma unroll
        for (int nt = 0; nt < 4; nt++) {
            const int r0 = bm + wm * 64 + mt * 16 + (lane >> 2);
            const int c  = bn + wn * 32 + nt * 8 + (lane & 3) * 2;
            const float bx = bias[c], by = bias[c + 1];
            #pragma unroll
            for (int half_ = 0; half_ < 2; half_++) {
                const int r = r0 + half_ * 8;
                if (r >= Mv) continue;
                float vx = acc[mt][nt][half_ * 2 + 0] + bx;
                float vy = acc[mt][nt][half_ * 2 + 1] + by;
                if (ACT == 1) { vx = gelu_exact(vx); vy = gelu_exact(vy); }
                if (RES) {
                    const float2 rr = *(const float2*)(R + (size_t)r * N + c);
                    vx += rr.x; vy += rr.y;
                }
                if (OUTH) {
                    *(__half2*)(Ch + (size_t)r * N + c) = __floats2half2_rn(vx, vy);
                } else {
                    float2 o; o.x = vx; o.y = vy;
                    *(float2*)(Cf + (size_t)r * N + c) = o;
                }
            }
        }
    }
}

// ---------------- window attention (2x2 QK + 2-row PV + precomputed bias) --
__global__ __launch_bounds__(128)
void win_attn(const __half* __restrict__ kvq, const float* __restrict__ biasM,
              const float* __restrict__ xin, float* __restrict__ x1)
{
    const int w = blockIdx.x;            // 0..1023
    const int h = blockIdx.y;            // 0..15
    const int b  = w >> 6;
    const int wi = w & 63;
    const int wr = wi >> 3, wc = wi & 7;

    __shared__ uint4 qs4[36][5];
    __shared__ uint4 ks4[37][5];
    __shared__ uint4 vs4[37][5];
    __shared__ float sc[36][37];

    const int tid = threadIdx.x;

    // ---- load (16B vectors, coalesced) ----
    for (int idx = tid; idx < 37 * 4; idx += 128) {
        const int m = idx >> 2, c = idx & 3;
        size_t row;
        if (m < 36) {
            const int r = m / 6, cc = m % 6;
            row = (size_t)(b * Lc + (wr * 6 + r) * 48 + wc * 6 + cc);
        } else {
            row = (size_t)(NTOK + b);
        }
        const uint4* base = (const uint4*)(kvq + row * NKVQ + h * 32);
        ks4[m][c] = base[c];
        vs4[m][c] = base[c + DIMc / 8];
        if (m < 36) qs4[m][c] = base[c + 2 * (DIMc / 8)];
    }
    __syncthreads();

    const float* biasH = biasM + h * 1332;

    // ---- QK^T + bias, 2x2 register tiling ----
    for (int t = tid; t < 18 * 19; t += 128) {
        const int mq0 = (t / 19) * 2;
        const int mk0 = (t % 19) * 2;
        const int mk1 = (mk0 + 1 < 37) ? (mk0 + 1) : 36;
        float a00 = 0.f, a01 = 0.f, a10 = 0.f, a11 = 0.f;
        #pragma unroll
        for (int c = 0; c < 4; c++) {
            const uint4 q0 = qs4[mq0][c],   q1 = qs4[mq0 + 1][c];
            const uint4 k0 = ks4[mk0][c],   k1 = ks4[mk1][c];
            const __half2* q0h = (const __half2*)&q0;
            const __half2* q1h = (const __half2*)&q1;
            const __half2* k0h = (const __half2*)&k0;
            const __half2* k1h = (const __half2*)&k1;
            #pragma unroll
            for (int j = 0; j < 4; j++) {
                const float2 qa = __half22float2(q0h[j]);
                const float2 qb = __half22float2(q1h[j]);
                const float2 ka = __half22float2(k0h[j]);
                const float2 kb = __half22float2(k1h[j]);
                a00 = fmaf(qa.x, ka.x, a00); a00 = fmaf(qa.y, ka.y, a00);
                a01 = fmaf(qa.x, kb.x, a01); a01 = fmaf(qa.y, kb.y, a01);
                a10 = fmaf(qb.x, ka.x, a10); a10 = fmaf(qb.y, ka.y, a10);
                a11 = fmaf(qb.x, kb.x, a11); a11 = fmaf(qb.y, kb.y, a11);
            }
        }
        sc[mq0][mk0]     = a00 * SCALEc + biasH[mq0 * 37 + mk0];
        sc[mq0 + 1][mk0] = a10 * SCALEc + biasH[(mq0 + 1) * 37 + mk0];
        if (mk0 + 1 < 37) {
            sc[mq0][mk0 + 1]     = a01 * SCALEc + biasH[mq0 * 37 + mk0 + 1];
            sc[mq0 + 1][mk0 + 1] = a11 * SCALEc + biasH[(mq0 + 1) * 37 + mk0 + 1];
        }
    }
    __syncthreads();

    // ---- softmax (per query row) ----
    if (tid < 36) {
        float mx = -1e30f;
        #pragma unroll
        for (int k = 0; k < 37; k++) mx = fmaxf(mx, sc[tid][k]);
        float sum = 0.0f;
        #pragma unroll
        for (int k = 0; k < 37; k++) { const float e = expf(sc[tid][k] - mx); sc[tid][k] = e; sum += e; }
        const float inv = 1.0f / sum;
        #pragma unroll
        for (int k = 0; k < 37; k++) sc[tid][k] *= inv;
    }
    __syncthreads();

    // ---- PV + residual, 2-row register tiling ----
    for (int p = tid; p < 18 * 4; p += 128) {
        const int m0 = (p >> 2) * 2, c = p & 3;
        float acc0[8] = {}, acc1[8] = {};
        #pragma unroll 4
        for (int k = 0; k < 37; k++) {
            const float w0 = sc[m0][k];
            const float w1 = sc[m0 + 1][k];
            const uint4 vv = vs4[k][c];
            const __half2* vh = (const __half2*)&vv;
            #pragma unroll
            for (int j = 0; j < 4; j++) {
                const float2 vf = __half22float2(vh[j]);
                acc0[2*j]   = fmaf(w0, vf.x, acc0[2*j]);
                acc0[2*j+1] = fmaf(w0, vf.y, acc0[2*j+1]);
                acc1[2*j]   = fmaf(w1, vf.x, acc1[2*j]);
                acc1[2*j+1] = fmaf(w1, vf.y, acc1[2*j+1]);
            }
        }
        #pragma unroll
        for (int i = 0; i < 2; i++) {
            const int m = m0 + i;
            const float* acc = (i == 0) ? acc0 : acc1;
            const int r = m / 6, cc = m % 6;
            const int l = (wr * 6 + r) * 48 + wc * 6 + cc;
            const size_t o = (size_t)(b * Lc + l) * DIMc + h * 32 + c * 8;
            float4 i0 = *(const float4*)(xin + o);
            float4 i1 = *(const float4*)(xin + o + 4);
            i0.x += acc[0]; i0.y += acc[1]; i0.z += acc[2]; i0.w += acc[3];
            i1.x += acc[4]; i1.y += acc[5]; i1.z += acc[6]; i1.w += acc[7];
            *(float4*)(x1 + o) = i0;
            *(float4*)(x1 + o + 4) = i1;
        }
    }
}

// ---------------- global-token attention: one block per (b, h) -------------
__global__ __launch_bounds__(256)
void glob_attn(const __half* __restrict__ kvq,
               const float* __restrict__ xavg_in, float* __restrict__ x1)
{
    const int b = blockIdx.x, h = blockIdx.y;
    __shared__ float qsh[32];
    __shared__ float wgt[Lc];
    __shared__ float red[8];
    const int tid = threadIdx.x, lane = tid & 31, wn = tid >> 5;

    if (tid < 32)
        qsh[tid] = __half2float(kvq[(size_t)(NTOK + b) * NKVQ + 2 * DIMc + h * 32 + tid]) * SCALEc;
    __syncthreads();

    float lmax = -1e30f;
    for (int k = tid; k < Lc; k += 256) {
        const __half2* kp = (const __half2*)(kvq + (size_t)(b * Lc + k) * NKVQ + h * 32);
        float acc = 0.0f;
        #pragma unroll
        for (int d2 = 0; d2 < 16; d2++) {
            const float2 kk = __half22float2(kp[d2]);
            acc = fmaf(qsh[d2*2+0], kk.x, acc);
            acc = fmaf(qsh[d2*2+1], kk.y, acc);
        }
        wgt[k] = acc;
        lmax = fmaxf(lmax, acc);
    }
    #pragma unroll
    for (int o = 16; o; o >>= 1) lmax = fmaxf(lmax, __shfl_xor_sync(0xffffffffu, lmax, o));
    if (lane == 0) red[wn] = lmax;
    __syncthreads();
    float gmax = red[0];
    #pragma unroll
    for (int i = 1; i < 8; i++) gmax = fmaxf(gmax, red[i]);
    __syncthreads();

    float lsum = 0.0f;
    for (int k = tid; k < Lc; k += 256) {
        const float e = expf(wgt[k] - gmax);
        wgt[k] = e;
        lsum += e;
    }
    #pragma unroll
    for (int o = 16; o; o >>= 1) lsum += __shfl_xor_sync(0xffffffffu, lsum, o);
    if (lane == 0) red[wn] = lsum;
    __syncthreads();
    float gsum = 0.0f;
    #pragma unroll
    for (int i = 0; i < 8; i++) gsum += red[i];
    const float inv = 1.0f / gsum;

    float acc[4] = {0.f, 0.f, 0.f, 0.f};
    for (int k = lane; k < Lc; k += 32) {
        const float wk = wgt[k];
        const __half2* vv = (const __half2*)(kvq + (size_t)(b * Lc + k) * NKVQ + DIMc + h * 32 + wn * 4);
        const float2 v0 = __half22float2(vv[0]);
        const float2 v1 = __half22float2(vv[1]);
        acc[0] = fmaf(wk, v0.x, acc[0]);
        acc[1] = fmaf(wk, v0.y, acc[1]);
        acc[2] = fmaf(wk, v1.x, acc[2]);
        acc[3] = fmaf(wk, v1.y, acc[3]);
    }
    #pragma unroll
    for (int j = 0; j < 4; j++) {
        #pragma unroll
        for (int o = 16; o; o >>= 1) acc[j] += __shfl_xor_sync(0xffffffffu, acc[j], o);
    }
    if (lane == 0) {
        #pragma unroll
        for (int j = 0; j < 4; j++) {
            const int c = h * 32 + wn * 4 + j;
            x1[(size_t)(NTOK + b) * DIMc + c] = xavg_in[(size_t)b * DIMc + c] + acc[j] * inv;
        }
    }
}

// ---------------------------------------------------------------------------
extern "C" void kernel_launch(void* const* d_in, const int* in_sizes, int n_in,
                              void* d_out, int out_size)
{
    const float* x     = (const float*)d_in[0];
    const float* xavg  = (const float*)d_in[1];
    const float* w_kv  = (const float*)d_in[2];
    const float* b_kv  = (const float*)d_in[3];
    const float* w_q   = (const float*)d_in[4];
    const float* b_q   = (const float*)d_in[5];
    const float* table = (const float*)d_in[6];
    const float* g1    = (const float*)d_in[7];
    const float* be1   = (const float*)d_in[8];
    const float* g2    = (const float*)d_in[9];
    const float* be2   = (const float*)d_in[10];
    const float* w_fc1 = (const float*)d_in[11];
    const float* b_fc1 = (const float*)d_in[12];
    const float* w_fc2 = (const float*)d_in[13];
    const float* b_fc2 = (const float*)d_in[14];
    float* out = (float*)d_out;

    __half *xnh, *kvqh, *hbuf, *wkvqT, *wfc1T, *wfc2T;
    float *x1, *bkvq, *biasM;
    cudaGetSymbolAddress((void**)&xnh,    g_xnh);
    cudaGetSymbolAddress((void**)&kvqh,   g_kvqh);
    cudaGetSymbolAddress((void**)&x1,     g_x1);
    cudaGetSymbolAddress((void**)&hbuf,   g_h);
    cudaGetSymbolAddress((void**)&wkvqT,  g_wkvqT);
    cudaGetSymbolAddress((void**)&bkvq,   g_bkvq);
    cudaGetSymbolAddress((void**)&wfc1T,  g_wfc1T);
    cudaGetSymbolAddress((void**)&wfc2T,  g_wfc2T);
    cudaGetSymbolAddress((void**)&biasM,  g_biasM);

    // dynamic smem: 4 stages x 256 rows x 40 halfs x 2B = 81920 B
    const int SMEM_SZ = 4 * 256 * 40 * 2;
    cudaFuncSetAttribute(hgemm<0, false, true >, cudaFuncAttributeMaxDynamicSharedMemorySize, SMEM_SZ);
    cudaFuncSetAttribute(hgemm<1, false, true >, cudaFuncAttributeMaxDynamicSharedMemorySize, SMEM_SZ);
    cudaFuncSetAttribute(hgemm<0, true,  false>, cudaFuncAttributeMaxDynamicSharedMemorySize, SMEM_SZ);

    // 0. fused weight prep (+ rel-pos bias matrix)
    prep_all<<<2818, dim3(32, 8)>>>(w_kv, w_q, w_fc1, w_fc2, b_kv, b_q, table,
                                    wkvqT, wfc1T, wfc2T, bkvq, biasM);

    // 1. LayerNorm 1 (image + global in one launch)
    ln_dual_h<<<NVALID, 128>>>(x, xavg, g1, be1, xnh);

    // 2. Fused kvq projection over ALL tokens in one GEMM
    hgemm<0, false, true><<<dim3(NKVQ/128, MPAD/128), 256, SMEM_SZ>>>(
        MPAD, NKVQ, DIMc, MPAD, xnh, wkvqT, bkvq, nullptr, kvqh);

    // 3. Attention (+ residual)
    win_attn <<<dim3(Bc*NWc, NHc), 128>>>(kvqh, biasM, x, x1);
    glob_attn<<<dim3(Bc,     NHc), 256>>>(kvqh, xavg, x1);

    // 4. LayerNorm 2
    ln_kernel_h<<<NVALID, 128>>>(x1, g2, be2, xnh);

    // 5. MLP (+ residual)
    hgemm<1, false, true ><<<dim3(HID/128,  MPAD/128), 256, SMEM_SZ>>>(
        MPAD, HID,  DIMc, MPAD,   xnh,  wfc1T, b_fc1, nullptr, hbuf);
    hgemm<0, true,  false><<<dim3(DIMc/128, MPAD/128), 256, SMEM_SZ>>>(
        MPAD, DIMc, HID,  NVALID, hbuf, wfc2T, b_fc2, x1, out);
}